// round 1
// baseline (speedup 1.0000x reference)
#include <cuda_runtime.h>
#include <cuda_bf16.h>
#include <cstdint>

// ---------------- constants ----------------
#define BATCH 4
#define T_TOTAL 35968706LL          // sum of all hypernet parameter counts
#define T2 (T_TOTAL / 2)            // 17,984,353 float2 columns (T_TOTAL is even)

// ---------------- device scratch (no allocation allowed) ----------------
__device__ float g_bufA[4 * 4 * 112 * 112];   // 200,704 floats (largest conv output)
__device__ float g_bufB[4 * 8 * 56 * 56];     // 100,352 floats
__device__ float g_q[BATCH * 16];             // quantized latents for the big GEMM

// ---------------- generic 4x4 stride-2 pad-1 conv ----------------
__global__ void conv_k(const float* __restrict__ in, const float* __restrict__ w,
                       const float* __restrict__ bias, float* __restrict__ out,
                       int Cin, int Cout, int Hin, int Hout, int act) {
    int total = BATCH * Cout * Hout * Hout;
    int tid = blockIdx.x * blockDim.x + threadIdx.x;
    if (tid >= total) return;
    int Win = Hin, Wout = Hout;
    int ow = tid % Wout;
    int oh = (tid / Wout) % Hout;
    int co = (tid / (Wout * Hout)) % Cout;
    int b  = tid / (Wout * Hout * Cout);

    float s = bias[co];
    int ih0 = oh * 2 - 1;
    int iw0 = ow * 2 - 1;
    for (int ci = 0; ci < Cin; ci++) {
        const float* ip = in + ((size_t)(b * Cin + ci) * Hin) * Win;
        const float* wp = w + ((size_t)(co * Cin + ci) * 16);
        #pragma unroll
        for (int kh = 0; kh < 4; kh++) {
            int ih = ih0 + kh;
            if ((unsigned)ih >= (unsigned)Hin) continue;
            const float* row = ip + (size_t)ih * Win;
            #pragma unroll
            for (int kw = 0; kw < 4; kw++) {
                int iw = iw0 + kw;
                if ((unsigned)iw >= (unsigned)Win) continue;
                s += row[iw] * wp[kh * 4 + kw];
            }
        }
    }
    if (act) s = (s >= 0.0f) ? s : 0.01f * s;
    out[tid] = s;
}

// ---------------- head: avgpool + fc1 + fc2 + VQ + loss ----------------
__global__ void head_k(const float* __restrict__ conv5,
                       const float* __restrict__ fc1_w, const float* __restrict__ fc1_b,
                       const float* __restrict__ fc2_w, const float* __restrict__ fc2_b,
                       const float* __restrict__ emb,
                       float* __restrict__ loss_out) {
    __shared__ float pooled[BATCH * 64];
    __shared__ float h[BATCH * 16];
    __shared__ float e[BATCH * 16];
    __shared__ float qv[BATCH * 16];
    int tid = threadIdx.x;   // 256 threads

    // AdaptiveAvgPool2d(1): mean over 7x7 per (b, c)
    {
        int b = tid / 64, c = tid % 64;
        const float* p = conv5 + (size_t)(b * 64 + c) * 49;
        float s = 0.0f;
        #pragma unroll
        for (int i = 0; i < 49; i++) s += p[i];
        pooled[b * 64 + c] = s * (1.0f / 49.0f);
    }
    __syncthreads();

    // fc1: [4,64] @ [16,64]^T + b, LeakyReLU
    if (tid < 64) {
        int b = tid / 16, i = tid % 16;
        float s = fc1_b[i];
        #pragma unroll 8
        for (int c = 0; c < 64; c++) s += pooled[b * 64 + c] * fc1_w[i * 64 + c];
        h[b * 16 + i] = (s >= 0.0f) ? s : 0.01f * s;
    }
    __syncthreads();

    // fc2: [4,16] @ [16,16]^T + b
    if (tid < 64) {
        int b = tid / 16, j = tid % 16;
        float s = fc2_b[j];
        #pragma unroll
        for (int i = 0; i < 16; i++) s += h[b * 16 + i] * fc2_w[j * 16 + i];
        e[b * 16 + j] = s;
    }
    __syncthreads();

    // VQ nearest codebook (DICT = 4)
    if (tid < BATCH) {
        int b = tid;
        float best = 3.402823e38f;
        int bi = 0;
        for (int j = 0; j < 4; j++) {
            float d = 0.0f;
            #pragma unroll
            for (int k = 0; k < 16; k++) {
                float diff = e[b * 16 + k] - emb[j * 16 + k];
                d += diff * diff;
            }
            if (d < best) { best = d; bi = j; }
        }
        #pragma unroll
        for (int k = 0; k < 16; k++) qv[b * 16 + k] = emb[bi * 16 + k];
    }
    __syncthreads();

    if (tid == 0) {
        float s = 0.0f;
        #pragma unroll
        for (int n = 0; n < 64; n++) {
            float d = qv[n] - e[n];
            s += d * d;
        }
        *loss_out = 1.25f * (s * (1.0f / 64.0f));   // q_lat + 0.25 * e_lat
        #pragma unroll
        for (int n = 0; n < 64; n++) g_q[n] = qv[n];
    }
}

// ---------------- the big one: flat = q @ W_all, [4,16] x [16, T_TOTAL] ----------------
// Pure HBM streaming: read 2.30 GB of W, write 0.575 GB of output.
// float2 vectorized (rows are 8B-aligned; T_TOTAL % 4 == 2 forbids float4 per-row).
__global__ void __launch_bounds__(256) hyper_gemm_k(const float* __restrict__ W,
                                                    float* __restrict__ out) {
    __shared__ float qs[64];
    if (threadIdx.x < 64) qs[threadIdx.x] = g_q[threadIdx.x];
    __syncthreads();

    long long t2 = (long long)blockIdx.x * blockDim.x + threadIdx.x;
    if (t2 >= T2) return;

    float2 w[16];
    #pragma unroll
    for (int k = 0; k < 16; k++) {
        w[k] = __ldg((const float2*)(W + (size_t)k * T_TOTAL) + t2);
    }

    #pragma unroll
    for (int b = 0; b < 4; b++) {
        float ax = 0.0f, ay = 0.0f;
        #pragma unroll
        for (int k = 0; k < 16; k++) {
            float qk = qs[b * 16 + k];
            ax = fmaf(qk, w[k].x, ax);
            ay = fmaf(qk, w[k].y, ay);
        }
        ((float2*)(out + (size_t)b * T_TOTAL))[t2] = make_float2(ax, ay);
    }
}

// ---------------- launch ----------------
extern "C" void kernel_launch(void* const* d_in, const int* in_sizes, int n_in,
                              void* d_out, int out_size) {
    const float* rgb   = (const float*)d_in[0];
    const float* cw1   = (const float*)d_in[1];
    const float* cb1   = (const float*)d_in[2];
    const float* cw2   = (const float*)d_in[3];
    const float* cb2   = (const float*)d_in[4];
    const float* cw3   = (const float*)d_in[5];
    const float* cb3   = (const float*)d_in[6];
    const float* cw4   = (const float*)d_in[7];
    const float* cb4   = (const float*)d_in[8];
    const float* cw5   = (const float*)d_in[9];
    const float* cb5   = (const float*)d_in[10];
    const float* fc1_w = (const float*)d_in[11];
    const float* fc1_b = (const float*)d_in[12];
    const float* fc2_w = (const float*)d_in[13];
    const float* fc2_b = (const float*)d_in[14];
    const float* emb   = (const float*)d_in[15];
    const float* W_all = (const float*)d_in[16];

    float* out = (float*)d_out;
    float* loss_ptr = out + (size_t)out_size - 1;   // flat first, loss scalar last

    float* bufA;  cudaGetSymbolAddress((void**)&bufA, g_bufA);
    float* bufB;  cudaGetSymbolAddress((void**)&bufB, g_bufB);

    const int TPB = 256;
    // conv1: 3->4, 224->112
    { int n = BATCH * 4 * 112 * 112;
      conv_k<<<(n + TPB - 1) / TPB, TPB>>>(rgb, cw1, cb1, bufA, 3, 4, 224, 112, 1); }
    // conv2: 4->8, 112->56
    { int n = BATCH * 8 * 56 * 56;
      conv_k<<<(n + TPB - 1) / TPB, TPB>>>(bufA, cw2, cb2, bufB, 4, 8, 112, 56, 1); }
    // conv3: 8->16, 56->28
    { int n = BATCH * 16 * 28 * 28;
      conv_k<<<(n + TPB - 1) / TPB, TPB>>>(bufB, cw3, cb3, bufA, 8, 16, 56, 28, 1); }
    // conv4: 16->32, 28->14
    { int n = BATCH * 32 * 14 * 14;
      conv_k<<<(n + TPB - 1) / TPB, TPB>>>(bufA, cw4, cb4, bufB, 16, 32, 28, 14, 1); }
    // conv5: 32->64, 14->7, NO activation
    { int n = BATCH * 64 * 7 * 7;
      conv_k<<<(n + TPB - 1) / TPB, TPB>>>(bufB, cw5, cb5, bufA, 32, 64, 14, 7, 0); }

    // head: pool + fc1 + fc2 + VQ + loss -> writes g_q and loss
    head_k<<<1, 256>>>(bufA, fc1_w, fc1_b, fc2_w, fc2_b, emb, loss_ptr);

    // big streaming GEMM: flat = q @ W_all
    { long long nblk = (T2 + TPB - 1) / TPB;
      hyper_gemm_k<<<(unsigned)nblk, TPB>>>(W_all, out); }
}

// round 2
// speedup vs baseline: 1.0381x; 1.0381x over previous
#include <cuda_runtime.h>
#include <cuda_bf16.h>
#include <cstdint>

// ---------------- constants ----------------
#define BATCH 4
#define T_TOTAL 35968706LL          // sum of all hypernet parameter counts
#define T2 (T_TOTAL / 2)            // 17,984,353 float2 columns (T_TOTAL is even)

// ---------------- device scratch (no allocation allowed) ----------------
__device__ float g_bufA[4 * 4 * 112 * 112];   // 200,704 floats (largest intermediate)
__device__ float g_bufB[4 * 8 * 56 * 56];     // 100,352 floats
__device__ float g_q[BATCH * 16];             // quantized latents for the big GEMM

// ---------------- templated 4x4 stride-2 pad-1 conv (full unroll) ----------------
// SPLIT > 1: split the Cin reduction into SPLIT partial outputs (summed later).
template<int CIN, int COUT, int HIN, int HOUT, bool ACT, int SPLIT, bool ADD_BIAS>
__global__ void __launch_bounds__(256) convT(const float* __restrict__ in,
                                             const float* __restrict__ w,
                                             const float* __restrict__ bias,
                                             float* __restrict__ out) {
    constexpr int CPS = CIN / SPLIT;
    int tid = blockIdx.x * 256 + threadIdx.x;
    constexpr int TOTAL = BATCH * COUT * HOUT * HOUT * SPLIT;
    if (tid >= TOTAL) return;

    int ow = tid % HOUT;
    int oh = (tid / HOUT) % HOUT;
    int co = (tid / (HOUT * HOUT)) % COUT;
    int b  = (tid / (HOUT * HOUT * COUT)) % BATCH;
    int s  = tid / (HOUT * HOUT * COUT * BATCH);

    float acc = ADD_BIAS ? bias[co] : 0.0f;
    int ih0 = oh * 2 - 1;
    int iw0 = ow * 2 - 1;

    const float* wbase = w + ((size_t)co * CIN + s * CPS) * 16;
    const float* ibase = in + ((size_t)b * CIN + s * CPS) * HIN * HIN;

    #pragma unroll
    for (int ci = 0; ci < CPS; ci++) {
        const float* ip = ibase + (size_t)ci * HIN * HIN;
        const float* wp = wbase + ci * 16;
        #pragma unroll
        for (int kh = 0; kh < 4; kh++) {
            int ih = ih0 + kh;
            bool rowok = (unsigned)ih < (unsigned)HIN;
            #pragma unroll
            for (int kw = 0; kw < 4; kw++) {
                int iw = iw0 + kw;
                bool ok = rowok && ((unsigned)iw < (unsigned)HIN);
                float v = ok ? __ldg(ip + (size_t)ih * HIN + iw) : 0.0f;
                acc = fmaf(v, __ldg(wp + kh * 4 + kw), acc);
            }
        }
    }
    if (ACT) acc = (acc >= 0.0f) ? acc : 0.01f * acc;
    out[tid] = acc;
}

// ---------------- head: sum conv5 partials + bias + avgpool + fc1 + fc2 + VQ + loss ----
// conv5 partials layout: p[s][b][co][49], s in {0,1}, no bias applied yet.
__global__ void head_k(const float* __restrict__ p,
                       const float* __restrict__ cb5,
                       const float* __restrict__ fc1_w, const float* __restrict__ fc1_b,
                       const float* __restrict__ fc2_w, const float* __restrict__ fc2_b,
                       const float* __restrict__ emb,
                       float* __restrict__ loss_out) {
    __shared__ float pooled[BATCH * 64];
    __shared__ float h[BATCH * 16];
    __shared__ float e[BATCH * 16];
    __shared__ float qv[BATCH * 16];
    int tid = threadIdx.x;   // 256 threads

    // pooled[b][c] = mean over 49 of (partial0 + partial1) + bias
    {
        int b = tid / 64, c = tid % 64;
        const float* p0 = p + (size_t)(0 * BATCH * 64 + b * 64 + c) * 49;
        const float* p1 = p + (size_t)(1 * BATCH * 64 + b * 64 + c) * 49;
        float sum = 0.0f;
        #pragma unroll
        for (int i = 0; i < 49; i++) sum += p0[i] + p1[i];
        pooled[b * 64 + c] = sum * (1.0f / 49.0f) + cb5[c];
    }
    __syncthreads();

    // fc1: [4,64] @ [16,64]^T + b, LeakyReLU
    if (tid < 64) {
        int b = tid / 16, i = tid % 16;
        float s = fc1_b[i];
        #pragma unroll
        for (int c = 0; c < 64; c++) s += pooled[b * 64 + c] * fc1_w[i * 64 + c];
        h[b * 16 + i] = (s >= 0.0f) ? s : 0.01f * s;
    }
    __syncthreads();

    // fc2: [4,16] @ [16,16]^T + b
    if (tid < 64) {
        int b = tid / 16, j = tid % 16;
        float s = fc2_b[j];
        #pragma unroll
        for (int i = 0; i < 16; i++) s += h[b * 16 + i] * fc2_w[j * 16 + i];
        e[b * 16 + j] = s;
    }
    __syncthreads();

    // VQ nearest codebook (DICT = 4)
    if (tid < BATCH) {
        int b = tid;
        float best = 3.402823e38f;
        int bi = 0;
        for (int j = 0; j < 4; j++) {
            float d = 0.0f;
            #pragma unroll
            for (int k = 0; k < 16; k++) {
                float diff = e[b * 16 + k] - emb[j * 16 + k];
                d += diff * diff;
            }
            if (d < best) { best = d; bi = j; }
        }
        #pragma unroll
        for (int k = 0; k < 16; k++) qv[b * 16 + k] = emb[bi * 16 + k];
    }
    __syncthreads();

    if (tid == 0) {
        float s = 0.0f;
        #pragma unroll
        for (int n = 0; n < 64; n++) {
            float d = qv[n] - e[n];
            s += d * d;
        }
        *loss_out = 1.25f * (s * (1.0f / 64.0f));   // q_lat + 0.25 * e_lat
        #pragma unroll
        for (int n = 0; n < 64; n++) g_q[n] = qv[n];
    }
}

// ---------------- the big one: flat = q @ W_all, [4,16] x [16, T_TOTAL] ----------------
// Pure HBM streaming: read 2.30 GB of W, write 0.575 GB of output.
// float2 vectorized (rows are 8B-aligned; T_TOTAL % 4 == 2 forbids float4 per-row).
__global__ void __launch_bounds__(256) hyper_gemm_k(const float* __restrict__ W,
                                                    float* __restrict__ out) {
    __shared__ float qs[64];
    if (threadIdx.x < 64) qs[threadIdx.x] = g_q[threadIdx.x];
    __syncthreads();

    long long t2 = (long long)blockIdx.x * blockDim.x + threadIdx.x;
    if (t2 >= T2) return;

    float2 w[16];
    #pragma unroll
    for (int k = 0; k < 16; k++) {
        w[k] = __ldg((const float2*)(W + (size_t)k * T_TOTAL) + t2);
    }

    #pragma unroll
    for (int b = 0; b < 4; b++) {
        float ax = 0.0f, ay = 0.0f;
        #pragma unroll
        for (int k = 0; k < 16; k++) {
            float qk = qs[b * 16 + k];
            ax = fmaf(qk, w[k].x, ax);
            ay = fmaf(qk, w[k].y, ay);
        }
        ((float2*)(out + (size_t)b * T_TOTAL))[t2] = make_float2(ax, ay);
    }
}

// ---------------- launch ----------------
extern "C" void kernel_launch(void* const* d_in, const int* in_sizes, int n_in,
                              void* d_out, int out_size) {
    const float* rgb   = (const float*)d_in[0];
    const float* cw1   = (const float*)d_in[1];
    const float* cb1   = (const float*)d_in[2];
    const float* cw2   = (const float*)d_in[3];
    const float* cb2   = (const float*)d_in[4];
    const float* cw3   = (const float*)d_in[5];
    const float* cb3   = (const float*)d_in[6];
    const float* cw4   = (const float*)d_in[7];
    const float* cb4   = (const float*)d_in[8];
    const float* cw5   = (const float*)d_in[9];
    const float* cb5   = (const float*)d_in[10];
    const float* fc1_w = (const float*)d_in[11];
    const float* fc1_b = (const float*)d_in[12];
    const float* fc2_w = (const float*)d_in[13];
    const float* fc2_b = (const float*)d_in[14];
    const float* emb   = (const float*)d_in[15];
    const float* W_all = (const float*)d_in[16];

    float* out = (float*)d_out;
    float* loss_ptr = out + (size_t)out_size - 1;   // flat first, loss scalar last

    float* bufA;  cudaGetSymbolAddress((void**)&bufA, g_bufA);
    float* bufB;  cudaGetSymbolAddress((void**)&bufB, g_bufB);

    // conv1: 3->4,  224->112, out bufA (200704)
    convT<3, 4, 224, 112, true, 1, true><<<784, 256>>>(rgb, cw1, cb1, bufA);
    // conv2: 4->8,  112->56,  out bufB (100352)
    convT<4, 8, 112, 56, true, 1, true><<<392, 256>>>(bufA, cw2, cb2, bufB);
    // conv3: 8->16, 56->28,   out bufA (50176)
    convT<8, 16, 56, 28, true, 1, true><<<196, 256>>>(bufB, cw3, cb3, bufA);
    // conv4: 16->32, 28->14,  out bufB (25088)
    convT<16, 32, 28, 14, true, 1, true><<<98, 256>>>(bufA, cw4, cb4, bufB);
    // conv5: 32->64, 14->7, NO activation, SPLIT=2 ci-halves, no bias (head adds it)
    // out bufA: [2][4][64][49] = 25088 partials
    convT<32, 64, 14, 7, false, 2, false><<<98, 256>>>(bufB, cw5, (const float*)nullptr, bufA);

    // head: partial-sum + bias + pool + fc1 + fc2 + VQ + loss -> writes g_q and loss
    head_k<<<1, 256>>>(bufA, cb5, fc1_w, fc1_b, fc2_w, fc2_b, emb, loss_ptr);

    // big streaming GEMM: flat = q @ W_all
    { const int TPB = 256;
      long long nblk = (T2 + TPB - 1) / TPB;
      hyper_gemm_k<<<(unsigned)nblk, TPB>>>(W_all, out); }
}